// round 1
// baseline (speedup 1.0000x reference)
#include <cuda_runtime.h>
#include <math.h>

#define NPLANETS      10
#define NEDGES_LOC    45
#define NT_PER_BLOCK  8
#define EDGES_PB      (NEDGES_LOC * NT_PER_BLOCK)   // 360
#define THREADS       384
#define HID           32

// tanh via EX2 + fast divide: rel err ~1e-6, 2 MUFU ops.
__device__ __forceinline__ float tanh_f(float x) {
    float ax = fabsf(x);
    float e  = __expf(-2.0f * ax);                 // in (0,1]
    float t  = __fdividef(1.0f - e, 1.0f + e);     // denom in [1,2]
    return copysignf(t, x);
}

__global__ void __launch_bounds__(THREADS)
learnforces_kernel(const float* __restrict__ D_V,
                   const float* __restrict__ logm,
                   const float* __restrict__ W1,
                   const float* __restrict__ b1,
                   const float* __restrict__ W2,
                   const float* __restrict__ b2,
                   const float* __restrict__ W3,
                   const float* __restrict__ b3,
                   const int*   __restrict__ senders,
                   const int*   __restrict__ receivers,
                   float*       __restrict__ out,
                   int ntime)
{
    __shared__ float sW1[3 * HID];              // rows 0..2 (sph features)
    __shared__ float sW2[HID * HID];            // 32x32
    __shared__ float sW3[HID * 4];              // padded rows [w0,w1,w2,0]
    __shared__ float sb2[HID];
    __shared__ float sb3[4];
    __shared__ float sbias1[NEDGES_LOC * HID];  // b1 + lm[r]*W1row3 + lm[s]*W1row4
    __shared__ float s_lm[NPLANETS];
    __shared__ float s_invm[NPLANETS];          // exp(-lm)
    __shared__ int   s_snd[NEDGES_LOC];
    __shared__ int   s_rcv[NEDGES_LOC];
    __shared__ float sacc[NT_PER_BLOCK * NPLANETS * 3];

    const int tid = threadIdx.x;

    // ---- cooperative setup ----
    for (int i = tid; i < 3 * HID; i += THREADS) sW1[i] = W1[i];
    for (int i = tid; i < HID * HID; i += THREADS) sW2[i] = W2[i];
    if (tid < HID) {
        sb2[tid] = b2[tid];
        sW3[tid * 4 + 0] = W3[tid * 3 + 0];
        sW3[tid * 4 + 1] = W3[tid * 3 + 1];
        sW3[tid * 4 + 2] = W3[tid * 3 + 2];
        sW3[tid * 4 + 3] = 0.0f;
    }
    if (tid < 4) sb3[tid] = (tid < 3) ? b3[tid] : 0.0f;
    if (tid < NEDGES_LOC) { s_snd[tid] = senders[tid]; s_rcv[tid] = receivers[tid]; }
    if (tid < NPLANETS) {
        float v = fminf(fmaxf(logm[tid], -12.0f), 12.0f);
        s_lm[tid]   = v;
        s_invm[tid] = expf(-v);
    }
    for (int i = tid; i < NT_PER_BLOCK * NPLANETS * 3; i += THREADS)
        sacc[i] = 0.0f;
    __syncthreads();

    // bias1 table (needs s_lm / s_snd / s_rcv)
    for (int i = tid; i < NEDGES_LOC * HID; i += THREADS) {
        int le = i >> 5;
        int j  = i & 31;
        sbias1[i] = b1[j] + s_lm[s_rcv[le]] * W1[3 * HID + j]
                          + s_lm[s_snd[le]] * W1[4 * HID + j];
    }
    __syncthreads();

    // ---- per-edge compute ----
    const int  t_local = tid / NEDGES_LOC;                 // 0..7 (garbage for tid>=360, masked)
    const int  le      = tid - t_local * NEDGES_LOC;       // 0..44
    const long t_glob  = (long)blockIdx.x * NT_PER_BLOCK + t_local;
    const bool valid   = (tid < EDGES_PB) && (t_glob < (long)ntime);

    if (valid) {
        long g = (long)blockIdx.x * EDGES_PB + tid;        // global edge index
        float x = D_V[g * 3 + 0];
        float y = D_V[g * 3 + 1];
        float z = D_V[g * 3 + 2];

        float r2 = fmaf(x, x, fmaf(y, y, z * z));
        float r  = sqrtf(r2);
        float ct = fminf(fmaxf(__fdividef(z, r), -1.0f), 1.0f);
        float th = acosf(ct);
        float ph = atan2f(y, x);

        // layer 1: h1 = tanh(r*W1r0 + th*W1r1 + ph*W1r2 + bias1[le])
        float h1[HID];
        {
            const float4* bia = (const float4*)(sbias1 + le * HID);
            const float4* a0  = (const float4*)(sW1);
            const float4* a1  = (const float4*)(sW1 + HID);
            const float4* a2  = (const float4*)(sW1 + 2 * HID);
#pragma unroll
            for (int q = 0; q < HID / 4; q++) {
                float4 bb = bia[q], w0 = a0[q], w1 = a1[q], w2 = a2[q];
                h1[4*q+0] = tanh_f(fmaf(r, w0.x, fmaf(th, w1.x, fmaf(ph, w2.x, bb.x))));
                h1[4*q+1] = tanh_f(fmaf(r, w0.y, fmaf(th, w1.y, fmaf(ph, w2.y, bb.y))));
                h1[4*q+2] = tanh_f(fmaf(r, w0.z, fmaf(th, w1.z, fmaf(ph, w2.z, bb.z))));
                h1[4*q+3] = tanh_f(fmaf(r, w0.w, fmaf(th, w1.w, fmaf(ph, w2.w, bb.w))));
            }
        }

        // layer 2: acc[j] = b2[j] + sum_k h1[k] * W2[k][j]  (k-outer, row-contiguous float4)
        float acc[HID];
        {
            const float4* bb = (const float4*)sb2;
#pragma unroll
            for (int q = 0; q < HID / 4; q++) {
                float4 v = bb[q];
                acc[4*q+0] = v.x; acc[4*q+1] = v.y; acc[4*q+2] = v.z; acc[4*q+3] = v.w;
            }
#pragma unroll
            for (int k = 0; k < HID; k++) {
                float hk = h1[k];
                const float4* row = (const float4*)(sW2 + k * HID);
#pragma unroll
                for (int q = 0; q < HID / 4; q++) {
                    float4 w = row[q];
                    acc[4*q+0] = fmaf(hk, w.x, acc[4*q+0]);
                    acc[4*q+1] = fmaf(hk, w.y, acc[4*q+1]);
                    acc[4*q+2] = fmaf(hk, w.z, acc[4*q+2]);
                    acc[4*q+3] = fmaf(hk, w.w, acc[4*q+3]);
                }
            }
        }

        // layer 3: e = tanh(acc) @ W3 + b3
        float e0 = sb3[0], e1 = sb3[1], e2 = sb3[2];
        {
            const float4* w3 = (const float4*)sW3;
#pragma unroll
            for (int k = 0; k < HID; k++) {
                float hk = tanh_f(acc[k]);
                float4 w = w3[k];
                e0 = fmaf(hk, w.x, e0);
                e1 = fmaf(hk, w.y, e1);
                e2 = fmaf(hk, w.z, e2);
            }
        }

        // sph -> cart
        float st, ctq, sp, cp;
        sincosf(e1, &st, &ctq);
        sincosf(e2, &sp, &cp);
        float cx = e0 * st * cp;
        float cy = e0 * st * sp;
        float cz = e0 * ctq;

        // scatter: +e at receiver, -e at sender (block-local smem accumulate)
        float* base = sacc + t_local * (NPLANETS * 3);
        int rr = s_rcv[le], ss = s_snd[le];
        atomicAdd(base + rr * 3 + 0,  cx);
        atomicAdd(base + rr * 3 + 1,  cy);
        atomicAdd(base + rr * 3 + 2,  cz);
        atomicAdd(base + ss * 3 + 0, -cx);
        atomicAdd(base + ss * 3 + 1, -cy);
        atomicAdd(base + ss * 3 + 2, -cz);
    }
    __syncthreads();

    // ---- write accel = force * exp(-lm[p]) ----
    for (int i = tid; i < NT_PER_BLOCK * NPLANETS * 3; i += THREADS) {
        int  tl  = i / (NPLANETS * 3);
        int  rem = i - tl * (NPLANETS * 3);
        int  p   = rem / 3;
        long t   = (long)blockIdx.x * NT_PER_BLOCK + tl;
        if (t < (long)ntime)
            out[t * (NPLANETS * 3) + rem] = sacc[i] * s_invm[p];
    }
}

extern "C" void kernel_launch(void* const* d_in, const int* in_sizes, int n_in,
                              void* d_out, int out_size)
{
    const float* D_V       = (const float*)d_in[0];
    const float* logm      = (const float*)d_in[1];
    const float* W1        = (const float*)d_in[2];
    const float* b1        = (const float*)d_in[3];
    const float* W2        = (const float*)d_in[4];
    const float* b2        = (const float*)d_in[5];
    const float* b3        = (const float*)d_in[7];
    const float* W3        = (const float*)d_in[6];
    const int*   senders   = (const int*)d_in[8];
    const int*   receivers = (const int*)d_in[9];
    float*       out       = (float*)d_out;

    int nedges = in_sizes[8];                  // 45
    int ntime  = in_sizes[0] / (3 * nedges);   // 100000

    int grid = (ntime + NT_PER_BLOCK - 1) / NT_PER_BLOCK;
    learnforces_kernel<<<grid, THREADS>>>(D_V, logm, W1, b1, W2, b2, W3, b3,
                                          senders, receivers, out, ntime);
}